// round 14
// baseline (speedup 1.0000x reference)
#include <cuda_runtime.h>
#include <cuda_fp16.h>
#include <cstdint>

// ---------------------------------------------------------------------------
// v13 = R4 (447us, best) + EXACTLY ONE change: split gate accumulators to
// break the post-barrier dependent-mma chain.
//   L0: aA = bias + 8 ih(x) mma  (independent of barrier-fresh h0 -> issues
//       immediately at barrier release);  aB = 4 hh(h0) mma (after LDS).
//       Chain 12 -> max(8,4+LDS). Bias moved regs->smem to fund +8 acc regs.
//   L1: aA = bias + 4 ih1(h0);  aB = 4 hh1(h1). Chain 8 -> 4.
// Cell math (f32 tanh.approx), sync topology, x pipeline, staging, head:
// byte-identical to R4.
// ---------------------------------------------------------------------------

namespace {

constexpr int T_ = 512, I_ = 128, H_ = 64, E_ = 128, C_ = 100;
constexpr int BT = 8, NCTA = 128, NTHR = 512;

constexpr int SWI = 136;
constexpr int SWH = 72;
constexpr int SXS = 136;
constexpr int SHS = 72;

constexpr int OFF_WIH0 = 0;
constexpr int OFF_WHH0 = 69632;
constexpr int OFF_WIH1 = 106496;
constexpr int OFF_WHH1 = 143360;
constexpr int OFF_B0   = 180224;
constexpr int OFF_B1   = 181248;
constexpr int OFF_X    = 182272;   // 2 bufs * 2176B
constexpr int OFF_H0   = 186624;   // 2 bufs * 1152B
constexpr int OFF_H1   = 188928;
constexpr int OFF_HF   = 191232;
constexpr int OFF_E    = 193280;
constexpr int OFF_F    = 197376;
constexpr int SMEM_TOTAL = 201472;

#define BARRIER() asm volatile("bar.sync 0;" ::: "memory")

__device__ __forceinline__ float tanh_ap(float x) {
    float y;
    asm("tanh.approx.f32 %0, %1;" : "=f"(y) : "f"(x));
    return y;
}
__device__ __forceinline__ float fsig(float x) {
    return fmaf(0.5f, tanh_ap(0.5f * x), 0.5f);
}

__device__ __forceinline__ void mma4(float c[4], const uint32_t a[4],
                                     uint32_t b0, uint32_t b1) {
    asm volatile(
        "mma.sync.aligned.m16n8k16.row.col.f32.f16.f16.f32 "
        "{%0,%1,%2,%3},{%4,%5,%6,%7},{%8,%9},{%0,%1,%2,%3};\n"
        : "+f"(c[0]), "+f"(c[1]), "+f"(c[2]), "+f"(c[3])
        : "r"(a[0]), "r"(a[1]), "r"(a[2]), "r"(a[3]), "r"(b0), "r"(b1));
}

template <int KT, int S>
__device__ __forceinline__ void load_w(const half* __restrict__ sW, int wc, int g,
                                       int t, uint32_t f[KT][2][4]) {
#pragma unroll
    for (int kt = 0; kt < KT; kt++)
#pragma unroll
        for (int u = 0; u < 2; u++) {
            const half* p = sW + (wc * 32 + u * 16 + g) * S + kt * 16 + 2 * t;
            f[kt][u][0] = *(const uint32_t*)(p);
            f[kt][u][1] = *(const uint32_t*)(p + 8 * S);
            f[kt][u][2] = *(const uint32_t*)(p + 8);
            f[kt][u][3] = *(const uint32_t*)(p + 8 * S + 8);
        }
}

// L0: bias (from smem, 4 LDS off the critical path) -> aA; aB zeroed
__device__ __forceinline__ void acc_init_smem(float aA[2][4], float aB[2][4],
                                              const float* __restrict__ sBj) {
    float v00 = sBj[0], v01 = sBj[64], v10 = sBj[128], v11 = sBj[192];
    aA[0][0] = v00; aA[0][1] = v00; aA[0][2] = v01; aA[0][3] = v01;
    aA[1][0] = v10; aA[1][1] = v10; aA[1][2] = v11; aA[1][3] = v11;
#pragma unroll
    for (int u = 0; u < 2; u++)
#pragma unroll
        for (int e = 0; e < 4; e++) aB[u][e] = 0.f;
}

__device__ __forceinline__ void acc_set(float a[2][4], const float b[2][2]) {
#pragma unroll
    for (int u = 0; u < 2; u++) {
        a[u][0] = b[u][0]; a[u][1] = b[u][0];
        a[u][2] = b[u][1]; a[u][3] = b[u][1];
    }
}

__global__ void __launch_bounds__(NTHR, 1)
lstm_fused(const float* __restrict__ x,
           const float* __restrict__ Wih0, const float* __restrict__ Whh0,
           const float* __restrict__ bih0, const float* __restrict__ bhh0,
           const float* __restrict__ Wih1, const float* __restrict__ Whh1,
           const float* __restrict__ bih1, const float* __restrict__ bhh1,
           const float* __restrict__ Wproj, const float* __restrict__ bproj,
           const float* __restrict__ Wfc1, const float* __restrict__ bfc1,
           const float* __restrict__ Wfc2, const float* __restrict__ bfc2,
           float* __restrict__ out)
{
    extern __shared__ unsigned char smem[];
    half*  sWih0 = (half*)(smem + OFF_WIH0);
    half*  sWhh0 = (half*)(smem + OFF_WHH0);
    half*  sWih1 = (half*)(smem + OFF_WIH1);
    half*  sWhh1 = (half*)(smem + OFF_WHH1);
    float* sB0   = (float*)(smem + OFF_B0);
    float* sB1   = (float*)(smem + OFF_B1);
    half*  sX    = (half*)(smem + OFF_X);
    half*  sH0   = (half*)(smem + OFF_H0);
    half*  sH1   = (half*)(smem + OFF_H1);
    float* sHF   = (float*)(smem + OFF_HF);
    float* sE    = (float*)(smem + OFF_E);
    float* sF    = (float*)(smem + OFF_F);

    const int tid  = threadIdx.x;
    const int lane = tid & 31;
    const int w    = tid >> 5;
    const int wc   = w & 7;
    const int g    = lane >> 2;
    const int t    = lane & 3;
    const int b0r  = blockIdx.x * BT;

    // ---- stage permuted fp16 weights + fused biases ----
    for (int i = tid; i < 256 * 128; i += NTHR) {
        int p = i >> 7, k = i & 127;
        int m = (((p >> 4) & 1) * 2 + ((p >> 3) & 1)) * 64 + (p >> 5) * 8 + (p & 7);
        sWih0[p * SWI + k] = __float2half(Wih0[m * 128 + k]);
    }
    for (int i = tid; i < 256 * 64; i += NTHR) {
        int p = i >> 6, k = i & 63;
        int m = (((p >> 4) & 1) * 2 + ((p >> 3) & 1)) * 64 + (p >> 5) * 8 + (p & 7);
        sWhh0[p * SWH + k] = __float2half(Whh0[m * 64 + k]);
        sWih1[p * SWH + k] = __float2half(Wih1[m * 64 + k]);
        sWhh1[p * SWH + k] = __float2half(Whh1[m * 64 + k]);
    }
    for (int i = tid; i < 256; i += NTHR) {
        sB0[i] = bih0[i] + bhh0[i];
        sB1[i] = bih1[i] + bhh1[i];
    }
    for (int i = tid; i < 2 * BT * SHS; i += NTHR)
        sH1[i] = __float2half(0.f);

    // ---- x prefetch owned by L1 warps: warp = batch row, lane = 4 floats ----
    const int xr = wc, xi = lane * 4;
    const float* xrow = x + ((size_t)(b0r + xr) * T_) * I_ + xi;
    float4 xpre = make_float4(0.f, 0.f, 0.f, 0.f);
    if (w >= 8) {
        float4 xv = *(const float4*)(xrow);            // x(0) -> buf1
        half* xw = sX + BT * SXS;
        *(half2*)(xw + xr * SXS + xi)     = __floats2half2_rn(xv.x, xv.y);
        *(half2*)(xw + xr * SXS + xi + 2) = __floats2half2_rn(xv.z, xv.w);
        xpre = *(const float4*)(xrow + I_);            // x(1)
    }
    __syncthreads();

    const int n0 = 2 * t;
    const int j  = wc * 8 + g;

    if (w < 8) {
        // ================= layer-0 warps =================
        uint32_t fih0[8][2][4], fhh0[4][2][4];
        load_w<8, SWI>(sWih0, wc, g, t, fih0);
        load_w<4, SWH>(sWhh0, wc, g, t, fhh0);
        const float* sB0j = sB0 + j;
        float c00 = 0.f, c01 = 0.f;

        {   // prologue: t=0 cell (no recurrent term), single chain is fine
            float aA[2][4], aB[2][4];
            acc_init_smem(aA, aB, sB0j);
            const half* X = sX + BT * SXS;
#pragma unroll
            for (int kt = 0; kt < 8; kt++) {
                const half* p = X + g * SXS + kt * 16 + 2 * t;
                uint32_t b0 = *(const uint32_t*)(p);
                uint32_t b1 = *(const uint32_t*)(p + 8);
                mma4(aA[0], fih0[kt][0], b0, b1);
                mma4(aA[1], fih0[kt][1], b0, b1);
            }
            float i0 = fsig(aA[0][0]), i1 = fsig(aA[0][1]);
            float g0 = tanh_ap(aA[1][0]), g1 = tanh_ap(aA[1][1]);
            float o0 = fsig(aA[1][2]), o1 = fsig(aA[1][3]);
            c00 = i0 * g0; c01 = i1 * g1;
            sH0[n0 * SHS + j]       = __float2half(o0 * tanh_ap(c00));
            sH0[(n0 + 1) * SHS + j] = __float2half(o1 * tanh_ap(c01));
        }
        BARRIER();

        for (int k = 0; k < T_; k++) {
            const int p = k & 1;
            float aA[2][4], aB[2][4];
            acc_init_smem(aA, aB, sB0j);

            // chain A: bias + 8 ih(x) mma -- x is 2 barriers old, issues at
            // barrier release with no wait on the fresh h0 LDS.
            const half* X = sX + p * (BT * SXS);
#pragma unroll
            for (int kt = 0; kt < 8; kt++) {
                const half* q = X + g * SXS + kt * 16 + 2 * t;
                uint32_t b0 = *(const uint32_t*)(q);
                uint32_t b1 = *(const uint32_t*)(q + 8);
                mma4(aA[0], fih0[kt][0], b0, b1);
                mma4(aA[1], fih0[kt][1], b0, b1);
            }
            // chain B: 4 hh(h0) mma -- LDS of fresh h0 overlaps chain A
            const half* H0 = sH0 + p * (BT * SHS);
#pragma unroll
            for (int kt = 0; kt < 4; kt++) {
                const half* q = H0 + g * SHS + kt * 16 + 2 * t;
                uint32_t b0 = *(const uint32_t*)(q);
                uint32_t b1 = *(const uint32_t*)(q + 8);
                mma4(aB[0], fhh0[kt][0], b0, b1);
                mma4(aB[1], fhh0[kt][1], b0, b1);
            }
            float a0[4], a1[4];
#pragma unroll
            for (int e = 0; e < 4; e++) {
                a0[e] = aA[0][e] + aB[0][e];
                a1[e] = aA[1][e] + aB[1][e];
            }
            // L0 cell for t = k+1 (phantom at k = T_-1, harmless)
            float i0 = fsig(a0[0]), i1 = fsig(a0[1]);
            float f0 = fsig(a0[2]), f1 = fsig(a0[3]);
            float g0 = tanh_ap(a1[0]), g1 = tanh_ap(a1[1]);
            float o0 = fsig(a1[2]), o1 = fsig(a1[3]);
            c00 = f0 * c00 + i0 * g0;
            c01 = f1 * c01 + i1 * g1;
            half* h0w = sH0 + (1 - p) * (BT * SHS);
            h0w[n0 * SHS + j]       = __float2half(o0 * tanh_ap(c00));
            h0w[(n0 + 1) * SHS + j] = __float2half(o1 * tanh_ap(c01));
            BARRIER();
        }
    } else {
        // ================= layer-1 warps =================
        uint32_t fih1[4][2][4], fhh1[4][2][4];
        load_w<4, SWH>(sWih1, wc, g, t, fih1);
        load_w<4, SWH>(sWhh1, wc, g, t, fhh1);
        float bb1[2][2];
#pragma unroll
        for (int u = 0; u < 2; u++)
#pragma unroll
            for (int v = 0; v < 2; v++)
                bb1[u][v] = sB1[(2 * u + v) * 64 + wc * 8 + g];

        float c10 = 0.f, c11 = 0.f;

        {   // commit x(1) -> buf0, fetch x(2)
            half* xw = sX;
            *(half2*)(xw + xr * SXS + xi)     = __floats2half2_rn(xpre.x, xpre.y);
            *(half2*)(xw + xr * SXS + xi + 2) = __floats2half2_rn(xpre.z, xpre.w);
            xpre = *(const float4*)(xrow + 2 * (size_t)I_);
        }
        BARRIER();

        for (int k = 0; k < T_; k++) {
            const int p = k & 1;
            {   // x pipeline: commit x(k+2) -> buf 1-p, launch LDG x(k+3)
                half* xw = sX + (1 - p) * (BT * SXS);
                *(half2*)(xw + xr * SXS + xi)     = __floats2half2_rn(xpre.x, xpre.y);
                *(half2*)(xw + xr * SXS + xi + 2) = __floats2half2_rn(xpre.z, xpre.w);
                int tn = k + 3; if (tn > T_ - 1) tn = T_ - 1;
                xpre = *(const float4*)(xrow + (size_t)tn * I_);
            }
            float aA[2][4], aB[2][4];
            acc_set(aA, bb1);
#pragma unroll
            for (int u = 0; u < 2; u++)
#pragma unroll
                for (int e = 0; e < 4; e++) aB[u][e] = 0.f;

            // two independent 4-deep chains: ih1(h0) -> aA, hh1(h1) -> aB
            const half* H0 = sH0 + p * (BT * SHS);
            const half* H1 = sH1 + p * (BT * SHS);
#pragma unroll
            for (int kt = 0; kt < 4; kt++) {
                const half* q0 = H0 + g * SHS + kt * 16 + 2 * t;
                uint32_t b0 = *(const uint32_t*)(q0);
                uint32_t b1 = *(const uint32_t*)(q0 + 8);
                mma4(aA[0], fih1[kt][0], b0, b1);
                mma4(aA[1], fih1[kt][1], b0, b1);
                const half* q1 = H1 + g * SHS + kt * 16 + 2 * t;
                uint32_t d0 = *(const uint32_t*)(q1);
                uint32_t d1 = *(const uint32_t*)(q1 + 8);
                mma4(aB[0], fhh1[kt][0], d0, d1);
                mma4(aB[1], fhh1[kt][1], d0, d1);
            }
            float a0[4], a1[4];
#pragma unroll
            for (int e = 0; e < 4; e++) {
                a0[e] = aA[0][e] + aB[0][e];
                a1[e] = aA[1][e] + aB[1][e];
            }
            // L1 cell for t = k
            float i0 = fsig(a0[0]), i1 = fsig(a0[1]);
            float f0 = fsig(a0[2]), f1 = fsig(a0[3]);
            float g0 = tanh_ap(a1[0]), g1 = tanh_ap(a1[1]);
            float o0 = fsig(a1[2]), o1 = fsig(a1[3]);
            c10 = f0 * c10 + i0 * g0;
            c11 = f1 * c11 + i1 * g1;
            float h0v = o0 * tanh_ap(c10), h1v = o1 * tanh_ap(c11);
            half* h1w = sH1 + (1 - p) * (BT * SHS);
            h1w[n0 * SHS + j]       = __float2half(h0v);
            h1w[(n0 + 1) * SHS + j] = __float2half(h1v);
            if (k == T_ - 1) {
                sHF[n0 * H_ + j]       = h0v;
                sHF[(n0 + 1) * H_ + j] = h1v;
            }
            BARRIER();
        }
    }

    __syncthreads();

    // ---- head: proj -> relu -> fc1 -> relu -> fc2 ----
#pragma unroll
    for (int q = 0; q < 2; q++) {
        int idx = tid + q * NTHR;
        int r = idx >> 7, e = idx & 127;
        float a = bproj[e];
        const float* wp = Wproj + e * H_;
        const float* hp = sHF + r * H_;
#pragma unroll 8
        for (int kk = 0; kk < H_; kk++) a += hp[kk] * wp[kk];
        sE[r * E_ + e] = fmaxf(a, 0.f);
    }
    __syncthreads();
#pragma unroll
    for (int q = 0; q < 2; q++) {
        int idx = tid + q * NTHR;
        int r = idx >> 7, e = idx & 127;
        float a = bfc1[e];
        const float* wp = Wfc1 + e * E_;
        const float* hp = sE + r * E_;
#pragma unroll 8
        for (int kk = 0; kk < E_; kk++) a += hp[kk] * wp[kk];
        sF[r * E_ + e] = fmaxf(a, 0.f);
    }
    __syncthreads();
    for (int idx = tid; idx < BT * C_; idx += NTHR) {
        int r = idx / C_, c = idx - r * C_;
        float a = bfc2[c];
        const float* wp = Wfc2 + c * E_;
        const float* hp = sF + r * E_;
#pragma unroll 8
        for (int kk = 0; kk < E_; kk++) a += hp[kk] * wp[kk];
        out[(size_t)(b0r + r) * C_ + c] = a;
    }
}

}  // namespace

extern "C" void kernel_launch(void* const* d_in, const int* in_sizes, int n_in,
                              void* d_out, int out_size) {
    cudaFuncSetAttribute(lstm_fused, cudaFuncAttributeMaxDynamicSharedMemorySize,
                         SMEM_TOTAL);
    lstm_fused<<<NCTA, NTHR, SMEM_TOTAL>>>(
        (const float*)d_in[0],
        (const float*)d_in[1],  (const float*)d_in[2],
        (const float*)d_in[3],  (const float*)d_in[4],
        (const float*)d_in[5],  (const float*)d_in[6],
        (const float*)d_in[7],  (const float*)d_in[8],
        (const float*)d_in[9],  (const float*)d_in[10],
        (const float*)d_in[11], (const float*)d_in[12],
        (const float*)d_in[13], (const float*)d_in[14],
        (float*)d_out);
}

// round 15
// speedup vs baseline: 1.2021x; 1.2021x over previous
#include <cuda_runtime.h>
#include <cuda_fp16.h>
#include <cstdint>

// ---------------------------------------------------------------------------
// FINAL: R4 verbatim — the empirical optimum after 13 rounds of experiments.
// Fused persistent LSTM classifier: 128 CTAs x 512 threads, single wave.
// Layer-split warp specialization under one global bar.sync per time step:
//   warps 0-7:  layer-0 (W_ih0/W_hh0 fragments register-resident, L0 cell)
//   warps 8-15: layer-1 (W_ih1/W_hh1 fragments, L1 cell, x prefetch pipeline)
// Weights fp16 in registers for all 512 steps (gate rows permuted so each
// thread's mma accumulators hold i,f,g,o for its 2 batch x 1 hidden cells);
// c-state fp32 in registers; h via double-buffered smem (fp16);
// activations via tanh.approx.f32 (sigmoid as affine of tanh).
// Beaten-by-nothing ledger: LDSM (R5), decoupled barriers (R6), windowed
// pipelining (R7), functional 3-way split (R8), f16x2 cell (R9), cross-
// barrier SW pipelining (R10), Wih0 hoist to separate kernel (R11), exact
// micro-opts (R12), anti-phase cell (R13), acc split (R14) -- all slower.
// ---------------------------------------------------------------------------

namespace {

constexpr int T_ = 512, I_ = 128, H_ = 64, E_ = 128, C_ = 100;
constexpr int BT = 8, NCTA = 128, NTHR = 512;

constexpr int SWI = 136;   // W_ih0 row stride (halves), K=128 + 8 pad
constexpr int SWH = 72;    // K=64 weight row stride
constexpr int SXS = 136;   // x row stride   (LDS conflict-free)
constexpr int SHS = 72;    // h row stride   (LDS conflict-free)

constexpr int OFF_WIH0 = 0;        // 256*136*2 = 69632
constexpr int OFF_WHH0 = 69632;    // 256*72*2  = 36864
constexpr int OFF_WIH1 = 106496;
constexpr int OFF_WHH1 = 143360;
constexpr int OFF_B0   = 180224;   // 256 f32
constexpr int OFF_B1   = 181248;
constexpr int OFF_X    = 182272;   // 2 bufs * 8*136*2 = 4352
constexpr int OFF_H0   = 186624;   // 2 bufs * 8*72*2  = 2304
constexpr int OFF_H1   = 188928;
constexpr int OFF_HF   = 191232;   // 8*64 f32
constexpr int OFF_E    = 193280;   // 8*128 f32
constexpr int OFF_F    = 197376;
constexpr int SMEM_TOTAL = 201472;

#define BARRIER() asm volatile("bar.sync 0;" ::: "memory")

__device__ __forceinline__ float tanh_ap(float x) {
    float y;
    asm("tanh.approx.f32 %0, %1;" : "=f"(y) : "f"(x));
    return y;
}
__device__ __forceinline__ float fsig(float x) {
    return fmaf(0.5f, tanh_ap(0.5f * x), 0.5f);
}

__device__ __forceinline__ void mma4(float c[4], const uint32_t a[4],
                                     uint32_t b0, uint32_t b1) {
    asm volatile(
        "mma.sync.aligned.m16n8k16.row.col.f32.f16.f16.f32 "
        "{%0,%1,%2,%3},{%4,%5,%6,%7},{%8,%9},{%0,%1,%2,%3};\n"
        : "+f"(c[0]), "+f"(c[1]), "+f"(c[2]), "+f"(c[3])
        : "r"(a[0]), "r"(a[1]), "r"(a[2]), "r"(a[3]), "r"(b0), "r"(b1));
}

// One-time: this warp's A-fragments (permuted W rows) -> registers.
template <int KT, int S>
__device__ __forceinline__ void load_w(const half* __restrict__ sW, int wc, int g,
                                       int t, uint32_t f[KT][2][4]) {
#pragma unroll
    for (int kt = 0; kt < KT; kt++)
#pragma unroll
        for (int u = 0; u < 2; u++) {
            const half* p = sW + (wc * 32 + u * 16 + g) * S + kt * 16 + 2 * t;
            f[kt][u][0] = *(const uint32_t*)(p);
            f[kt][u][1] = *(const uint32_t*)(p + 8 * S);
            f[kt][u][2] = *(const uint32_t*)(p + 8);
            f[kt][u][3] = *(const uint32_t*)(p + 8 * S + 8);
        }
}

__device__ __forceinline__ void acc_init(float a[2][4], const float b[2][2]) {
#pragma unroll
    for (int u = 0; u < 2; u++) {
        a[u][0] = b[u][0]; a[u][1] = b[u][0];
        a[u][2] = b[u][1]; a[u][3] = b[u][1];
    }
}

__global__ void __launch_bounds__(NTHR, 1)
lstm_fused(const float* __restrict__ x,
           const float* __restrict__ Wih0, const float* __restrict__ Whh0,
           const float* __restrict__ bih0, const float* __restrict__ bhh0,
           const float* __restrict__ Wih1, const float* __restrict__ Whh1,
           const float* __restrict__ bih1, const float* __restrict__ bhh1,
           const float* __restrict__ Wproj, const float* __restrict__ bproj,
           const float* __restrict__ Wfc1, const float* __restrict__ bfc1,
           const float* __restrict__ Wfc2, const float* __restrict__ bfc2,
           float* __restrict__ out)
{
    extern __shared__ unsigned char smem[];
    half*  sWih0 = (half*)(smem + OFF_WIH0);
    half*  sWhh0 = (half*)(smem + OFF_WHH0);
    half*  sWih1 = (half*)(smem + OFF_WIH1);
    half*  sWhh1 = (half*)(smem + OFF_WHH1);
    float* sB0   = (float*)(smem + OFF_B0);
    float* sB1   = (float*)(smem + OFF_B1);
    half*  sX    = (half*)(smem + OFF_X);
    half*  sH0   = (half*)(smem + OFF_H0);
    half*  sH1   = (half*)(smem + OFF_H1);
    float* sHF   = (float*)(smem + OFF_HF);
    float* sE    = (float*)(smem + OFF_E);
    float* sF    = (float*)(smem + OFF_F);

    const int tid  = threadIdx.x;
    const int lane = tid & 31;
    const int w    = tid >> 5;
    const int wc   = w & 7;           // column-warp index (hidden units wc*8+g)
    const int g    = lane >> 2;
    const int t    = lane & 3;
    const int b0r  = blockIdx.x * BT;

    // ---- stage permuted fp16 weights + fused biases (all 512 threads) ----
    // perm row p = wc*32 + u*16 + v*8 + r  <->  orig m = (2u+v)*64 + wc*8 + r
    for (int i = tid; i < 256 * 128; i += NTHR) {
        int p = i >> 7, k = i & 127;
        int m = (((p >> 4) & 1) * 2 + ((p >> 3) & 1)) * 64 + (p >> 5) * 8 + (p & 7);
        sWih0[p * SWI + k] = __float2half(Wih0[m * 128 + k]);
    }
    for (int i = tid; i < 256 * 64; i += NTHR) {
        int p = i >> 6, k = i & 63;
        int m = (((p >> 4) & 1) * 2 + ((p >> 3) & 1)) * 64 + (p >> 5) * 8 + (p & 7);
        sWhh0[p * SWH + k] = __float2half(Whh0[m * 64 + k]);
        sWih1[p * SWH + k] = __float2half(Wih1[m * 64 + k]);
        sWhh1[p * SWH + k] = __float2half(Whh1[m * 64 + k]);
    }
    for (int i = tid; i < 256; i += NTHR) {
        sB0[i] = bih0[i] + bhh0[i];
        sB1[i] = bih1[i] + bhh1[i];
    }
    for (int i = tid; i < 2 * BT * SHS; i += NTHR) {
        sH1[i] = __float2half(0.f);     // h1(-1) = 0
    }

    // ---- x pipeline owned by L1 warps (8-15): warp=batch row, lane=4 floats ----
    const int xr = wc, xi = lane * 4;
    const float* xrow = x + ((size_t)(b0r + xr) * T_) * I_ + xi;
    float4 xpre = make_float4(0.f, 0.f, 0.f, 0.f);
    if (w >= 8) {
        float4 xv = *(const float4*)(xrow);            // x(0) -> sX buf1
        half* xw = sX + BT * SXS;
        *(half2*)(xw + xr * SXS + xi)     = __floats2half2_rn(xv.x, xv.y);
        *(half2*)(xw + xr * SXS + xi + 2) = __floats2half2_rn(xv.z, xv.w);
        xpre = *(const float4*)(xrow + I_);            // x(1)
    }
    __syncthreads();                                   // (A)

    const int n0 = 2 * t;            // this thread's two batch rows
    const int j  = wc * 8 + g;       // this thread's hidden unit

    if (w < 8) {
        // ================= layer-0 warps =================
        uint32_t fih0[8][2][4], fhh0[4][2][4];
        load_w<8, SWI>(sWih0, wc, g, t, fih0);
        load_w<4, SWH>(sWhh0, wc, g, t, fhh0);
        float bb0[2][2];
#pragma unroll
        for (int u = 0; u < 2; u++)
#pragma unroll
            for (int v = 0; v < 2; v++)
                bb0[u][v] = sB0[(2 * u + v) * 64 + wc * 8 + g];

        float c00 = 0.f, c01 = 0.f;

        {   // prologue: t = 0 cell (h0(-1)=0 -> no recurrent term)
            float a[2][4];
            acc_init(a, bb0);
            const half* X = sX + BT * SXS;
#pragma unroll
            for (int kt = 0; kt < 8; kt++) {
                const half* p = X + g * SXS + kt * 16 + 2 * t;
                uint32_t b0 = *(const uint32_t*)(p);
                uint32_t b1 = *(const uint32_t*)(p + 8);
                mma4(a[0], fih0[kt][0], b0, b1);
                mma4(a[1], fih0[kt][1], b0, b1);
            }
            float i0 = fsig(a[0][0]), i1 = fsig(a[0][1]);
            float g0 = tanh_ap(a[1][0]), g1 = tanh_ap(a[1][1]);
            float o0 = fsig(a[1][2]), o1 = fsig(a[1][3]);
            c00 = i0 * g0; c01 = i1 * g1;
            sH0[n0 * SHS + j]       = __float2half(o0 * tanh_ap(c00));
            sH0[(n0 + 1) * SHS + j] = __float2half(o1 * tanh_ap(c01));
        }
        BARRIER();                                      // S1

        for (int k = 0; k < T_; k++) {
            const int p = k & 1;
            float a[2][4];
            acc_init(a, bb0);
            const half* H0 = sH0 + p * (BT * SHS);
#pragma unroll
            for (int kt = 0; kt < 4; kt++) {
                const half* q = H0 + g * SHS + kt * 16 + 2 * t;
                uint32_t b0 = *(const uint32_t*)(q);
                uint32_t b1 = *(const uint32_t*)(q + 8);
                mma4(a[0], fhh0[kt][0], b0, b1);
                mma4(a[1], fhh0[kt][1], b0, b1);
            }
            const half* X = sX + p * (BT * SXS);
#pragma unroll
            for (int kt = 0; kt < 8; kt++) {
                const half* q = X + g * SXS + kt * 16 + 2 * t;
                uint32_t b0 = *(const uint32_t*)(q);
                uint32_t b1 = *(const uint32_t*)(q + 8);
                mma4(a[0], fih0[kt][0], b0, b1);
                mma4(a[1], fih0[kt][1], b0, b1);
            }
            // L0 cell for t = k+1 (phantom at k = T_-1, harmless)
            float i0 = fsig(a[0][0]), i1 = fsig(a[0][1]);
            float f0 = fsig(a[0][2]), f1 = fsig(a[0][3]);
            float g0 = tanh_ap(a[1][0]), g1 = tanh_ap(a[1][1]);
            float o0 = fsig(a[1][2]), o1 = fsig(a[1][3]);
            c00 = f0 * c00 + i0 * g0;
            c01 = f1 * c01 + i1 * g1;
            half* h0w = sH0 + (1 - p) * (BT * SHS);
            h0w[n0 * SHS + j]       = __float2half(o0 * tanh_ap(c00));
            h0w[(n0 + 1) * SHS + j] = __float2half(o1 * tanh_ap(c01));
            BARRIER();
        }
    } else {
        // ================= layer-1 warps =================
        uint32_t fih1[4][2][4], fhh1[4][2][4];
        load_w<4, SWH>(sWih1, wc, g, t, fih1);
        load_w<4, SWH>(sWhh1, wc, g, t, fhh1);
        float bb1[2][2];
#pragma unroll
        for (int u = 0; u < 2; u++)
#pragma unroll
            for (int v = 0; v < 2; v++)
                bb1[u][v] = sB1[(2 * u + v) * 64 + wc * 8 + g];

        float c10 = 0.f, c11 = 0.f;

        {   // commit x(1) -> sX buf0, fetch x(2)
            half* xw = sX;
            *(half2*)(xw + xr * SXS + xi)     = __floats2half2_rn(xpre.x, xpre.y);
            *(half2*)(xw + xr * SXS + xi + 2) = __floats2half2_rn(xpre.z, xpre.w);
            xpre = *(const float4*)(xrow + 2 * (size_t)I_);
        }
        BARRIER();                                      // S1

        for (int k = 0; k < T_; k++) {
            const int p = k & 1;
            float a[2][4];
            acc_init(a, bb1);
            const half* H0 = sH0 + p * (BT * SHS);
            const half* H1 = sH1 + p * (BT * SHS);
#pragma unroll
            for (int kt = 0; kt < 4; kt++) {
                const half* q0 = H0 + g * SHS + kt * 16 + 2 * t;
                uint32_t b0 = *(const uint32_t*)(q0);
                uint32_t b1 = *(const uint32_t*)(q0 + 8);
                mma4(a[0], fih1[kt][0], b0, b1);
                mma4(a[1], fih1[kt][1], b0, b1);
                const half* q1 = H1 + g * SHS + kt * 16 + 2 * t;
                uint32_t d0 = *(const uint32_t*)(q1);
                uint32_t d1 = *(const uint32_t*)(q1 + 8);
                mma4(a[0], fhh1[kt][0], d0, d1);
                mma4(a[1], fhh1[kt][1], d0, d1);
            }
            {   // x pipeline: commit x(k+2) -> buf 1-p, fetch x(k+3)
                half* xw = sX + (1 - p) * (BT * SXS);
                *(half2*)(xw + xr * SXS + xi)     = __floats2half2_rn(xpre.x, xpre.y);
                *(half2*)(xw + xr * SXS + xi + 2) = __floats2half2_rn(xpre.z, xpre.w);
                int tn = k + 3; if (tn > T_ - 1) tn = T_ - 1;
                xpre = *(const float4*)(xrow + (size_t)tn * I_);
            }
            // L1 cell for t = k
            float i0 = fsig(a[0][0]), i1 = fsig(a[0][1]);
            float f0 = fsig(a[0][2]), f1 = fsig(a[0][3]);
            float g0 = tanh_ap(a[1][0]), g1 = tanh_ap(a[1][1]);
            float o0 = fsig(a[1][2]), o1 = fsig(a[1][3]);
            c10 = f0 * c10 + i0 * g0;
            c11 = f1 * c11 + i1 * g1;
            float h0v = o0 * tanh_ap(c10), h1v = o1 * tanh_ap(c11);
            half* h1w = sH1 + (1 - p) * (BT * SHS);
            h1w[n0 * SHS + j]       = __float2half(h0v);
            h1w[(n0 + 1) * SHS + j] = __float2half(h1v);
            if (k == T_ - 1) {
                sHF[n0 * H_ + j]       = h0v;
                sHF[(n0 + 1) * H_ + j] = h1v;
            }
            BARRIER();
        }
    }

    // ---- head (all 512 threads): proj -> relu -> fc1 -> relu -> fc2 ----
#pragma unroll
    for (int q = 0; q < 2; q++) {
        int idx = tid + q * NTHR;                 // 1024 outputs
        int r = idx >> 7, e = idx & 127;
        float a = bproj[e];
        const float* wp = Wproj + e * H_;
        const float* hp = sHF + r * H_;
#pragma unroll 8
        for (int kk = 0; kk < H_; kk++) a += hp[kk] * wp[kk];
        sE[r * E_ + e] = fmaxf(a, 0.f);
    }
    __syncthreads();
#pragma unroll
    for (int q = 0; q < 2; q++) {
        int idx = tid + q * NTHR;
        int r = idx >> 7, e = idx & 127;
        float a = bfc1[e];
        const float* wp = Wfc1 + e * E_;
        const float* hp = sE + r * E_;
#pragma unroll 8
        for (int kk = 0; kk < E_; kk++) a += hp[kk] * wp[kk];
        sF[r * E_ + e] = fmaxf(a, 0.f);
    }
    __syncthreads();
    for (int idx = tid; idx < BT * C_; idx += NTHR) {
        int r = idx / C_, c = idx - r * C_;
        float a = bfc2[c];
        const float* wp = Wfc2 + c * E_;
        const float* hp = sF + r * E_;
#pragma unroll 8
        for (int kk = 0; kk < E_; kk++) a += hp[kk] * wp[kk];
        out[(size_t)(b0r + r) * C_ + c] = a;
    }
}

}  // namespace

extern "C" void kernel_launch(void* const* d_in, const int* in_sizes, int n_in,
                              void* d_out, int out_size) {
    cudaFuncSetAttribute(lstm_fused, cudaFuncAttributeMaxDynamicSharedMemorySize,
                         SMEM_TOTAL);
    lstm_fused<<<NCTA, NTHR, SMEM_TOTAL>>>(
        (const float*)d_in[0],
        (const float*)d_in[1],  (const float*)d_in[2],
        (const float*)d_in[3],  (const float*)d_in[4],
        (const float*)d_in[5],  (const float*)d_in[6],
        (const float*)d_in[7],  (const float*)d_in[8],
        (const float*)d_in[9],  (const float*)d_in[10],
        (const float*)d_in[11], (const float*)d_in[12],
        (const float*)d_in[13], (const float*)d_in[14],
        (float*)d_out);
}